// round 4
// baseline (speedup 1.0000x reference)
#include <cuda_runtime.h>

// ---------------------------------------------------------------------------
// Masked multi-level MSE loss (B=16, C=256, T=128, S in {80,40,20}):
//   L = mean_l [ sum((M_l * (p_l - t_l))^2) / (C * sum(M_l)) ]
//
// Single fused kernel. The concatenated float4 stream (lvl0|lvl1|lvl2) is
// split into 740 equal contiguous ranges (one wave, 5 blocks/SM). Each block
// walks its range in segments of constant (level, batch), rasterizes that
// batch's boxes into an SMEM mask, then streams pred/true with a 4x-unrolled
// loop (8 independent LDG.128 per thread per iteration). Mask-byte count
// accumulated alongside == C*sum(M) exactly. Last block finalizes.
// ---------------------------------------------------------------------------

#define NB 16
#define NT 128
#define NC 256
#define GRID_BLOCKS 740        // 148 SMs * 5 (matches __launch_bounds__ occ)
#define BLOCK_THREADS 256

#define L0_F4 6553600u         // 16*256*80*80/4
#define L1_F4 1638400u
#define L2_F4 409600u
#define TOT_F4 8601600ull

__device__ float g_pa[3][GRID_BLOCKS];
__device__ int   g_pc[3][GRID_BLOCKS];
__device__ unsigned g_ticket = 0;

// ---------------------------------------------------------------------------
__device__ __forceinline__ float block_sum_f(float v, float* sm) {
#pragma unroll
    for (int o = 16; o; o >>= 1) v += __shfl_down_sync(0xffffffffu, v, o);
    const int lane = threadIdx.x & 31, warp = threadIdx.x >> 5;
    if (lane == 0) sm[warp] = v;
    __syncthreads();
    v = (threadIdx.x < (BLOCK_THREADS / 32)) ? sm[threadIdx.x] : 0.f;
    if (warp == 0) {
#pragma unroll
        for (int o = 16; o; o >>= 1) v += __shfl_down_sync(0xffffffffu, v, o);
    }
    __syncthreads();
    return v;
}

__device__ __forceinline__ int block_sum_i(int v, int* sm) {
#pragma unroll
    for (int o = 16; o; o >>= 1) v += __shfl_down_sync(0xffffffffu, v, o);
    const int lane = threadIdx.x & 31, warp = threadIdx.x >> 5;
    if (lane == 0) sm[warp] = v;
    __syncthreads();
    v = (threadIdx.x < (BLOCK_THREADS / 32)) ? sm[threadIdx.x] : 0;
    if (warp == 0) {
#pragma unroll
        for (int o = 16; o; o >>= 1) v += __shfl_down_sync(0xffffffffu, v, o);
    }
    __syncthreads();
    return v;
}

// ---------------------------------------------------------------------------
struct SmemBox {
    int   nb;
    short xl[NT], xr[NT], yt[NT], yd[NT];
    unsigned char mask[NB == 16 ? 6400 : 6400];  // max S*S (80*80)
};

// Build the SMEM mask for (level S, batch b), then stream f4 range
// [li0, liend) of this level's pred/true arrays.
template <int S>
__device__ void do_segment(const float4* __restrict__ p,
                           const float4* __restrict__ q,
                           unsigned li0, unsigned liend, int b,
                           const float* __restrict__ bboxes,
                           const int* __restrict__ batch_idx,
                           SmemBox* sb, float& acc, int& cnt) {
    constexpr unsigned CH4 = (unsigned)S * (S / 4);  // f4 per channel image

    // ---- build mask (block-uniform control flow) ----
    __syncthreads();                    // previous segment's mask reads done
    if (threadIdx.x == 0) sb->nb = 0;
    __syncthreads();
    if (threadIdx.x < NT && batch_idx[threadIdx.x] == b) {
        const int t = threadIdx.x;
        const float fS = (float)S;
        int xc = (int)floorf(bboxes[t * 4 + 0] * fS);
        int yc = (int)floorf(bboxes[t * 4 + 1] * fS);
        int w  = (int)floorf(bboxes[t * 4 + 2] * fS);
        int h  = (int)floorf(bboxes[t * 4 + 3] * fS);
        int slot = atomicAdd(&sb->nb, 1);
        sb->xl[slot] = (short)max(xc - w / 2, 0);
        sb->yt[slot] = (short)max(yc - h / 2, 0);
        sb->xr[slot] = (short)min(xc + w / 2, S - 1);
        sb->yd[slot] = (short)min(yc + h / 2, S - 1);
    }
    __syncthreads();
    const int n = sb->nb;
    for (int c = threadIdx.x; c < S * S; c += BLOCK_THREADS) {
        const int y = c / S, x = c % S;
        int m = 0;
        for (int t = 0; t < n; t++) {
            m |= (x >= (int)sb->xl[t]) & (x <= (int)sb->xr[t]) &
                 (y >= (int)sb->yt[t]) & (y <= (int)sb->yd[t]);
        }
        sb->mask[c] = (unsigned char)m;
    }
    __syncthreads();

    // ---- stream (4x unrolled, 8 independent LDG.128 per thread) ----
    const unsigned char* __restrict__ mk = sb->mask;
    unsigned i = li0 + threadIdx.x;
    for (; i + 3u * BLOCK_THREADS < liend; i += 4u * BLOCK_THREADS) {
        const unsigned i0 = i, i1 = i + BLOCK_THREADS,
                       i2 = i + 2u * BLOCK_THREADS, i3 = i + 3u * BLOCK_THREADS;
        const uchar4 m0 = *(const uchar4*)(mk + 4u * (i0 % CH4));
        const uchar4 m1 = *(const uchar4*)(mk + 4u * (i1 % CH4));
        const uchar4 m2 = *(const uchar4*)(mk + 4u * (i2 % CH4));
        const uchar4 m3 = *(const uchar4*)(mk + 4u * (i3 % CH4));
        const float4 a0 = __ldg(p + i0);
        const float4 a1 = __ldg(p + i1);
        const float4 a2 = __ldg(p + i2);
        const float4 a3 = __ldg(p + i3);
        const float4 c0 = __ldg(q + i0);
        const float4 c1 = __ldg(q + i1);
        const float4 c2 = __ldg(q + i2);
        const float4 c3 = __ldg(q + i3);

        cnt += (int)m0.x + (int)m0.y + (int)m0.z + (int)m0.w
             + (int)m1.x + (int)m1.y + (int)m1.z + (int)m1.w
             + (int)m2.x + (int)m2.y + (int)m2.z + (int)m2.w
             + (int)m3.x + (int)m3.y + (int)m3.z + (int)m3.w;

        float d;
        d = a0.x - c0.x; acc = fmaf((float)m0.x * d, d, acc);
        d = a0.y - c0.y; acc = fmaf((float)m0.y * d, d, acc);
        d = a0.z - c0.z; acc = fmaf((float)m0.z * d, d, acc);
        d = a0.w - c0.w; acc = fmaf((float)m0.w * d, d, acc);
        d = a1.x - c1.x; acc = fmaf((float)m1.x * d, d, acc);
        d = a1.y - c1.y; acc = fmaf((float)m1.y * d, d, acc);
        d = a1.z - c1.z; acc = fmaf((float)m1.z * d, d, acc);
        d = a1.w - c1.w; acc = fmaf((float)m1.w * d, d, acc);
        d = a2.x - c2.x; acc = fmaf((float)m2.x * d, d, acc);
        d = a2.y - c2.y; acc = fmaf((float)m2.y * d, d, acc);
        d = a2.z - c2.z; acc = fmaf((float)m2.z * d, d, acc);
        d = a2.w - c2.w; acc = fmaf((float)m2.w * d, d, acc);
        d = a3.x - c3.x; acc = fmaf((float)m3.x * d, d, acc);
        d = a3.y - c3.y; acc = fmaf((float)m3.y * d, d, acc);
        d = a3.z - c3.z; acc = fmaf((float)m3.z * d, d, acc);
        d = a3.w - c3.w; acc = fmaf((float)m3.w * d, d, acc);
    }
    for (; i < liend; i += BLOCK_THREADS) {
        const uchar4 m0 = *(const uchar4*)(mk + 4u * (i % CH4));
        const float4 a0 = __ldg(p + i);
        const float4 c0 = __ldg(q + i);
        cnt += (int)m0.x + (int)m0.y + (int)m0.z + (int)m0.w;
        float d;
        d = a0.x - c0.x; acc = fmaf((float)m0.x * d, d, acc);
        d = a0.y - c0.y; acc = fmaf((float)m0.y * d, d, acc);
        d = a0.z - c0.z; acc = fmaf((float)m0.z * d, d, acc);
        d = a0.w - c0.w; acc = fmaf((float)m0.w * d, d, acc);
    }
}

// ---------------------------------------------------------------------------
__global__ void __launch_bounds__(BLOCK_THREADS, 5)
fused_kernel(const float4* __restrict__ p0, const float4* __restrict__ t0,
             const float4* __restrict__ p1, const float4* __restrict__ t1,
             const float4* __restrict__ p2, const float4* __restrict__ t2,
             const float* __restrict__ bboxes,
             const int* __restrict__ batch_idx,
             float* __restrict__ out) {
    __shared__ SmemBox sb;

    const unsigned long long lo = (unsigned long long)blockIdx.x * TOT_F4 / GRID_BLOCKS;
    const unsigned long long hi = (unsigned long long)(blockIdx.x + 1) * TOT_F4 / GRID_BLOCKS;

    float acc0 = 0.f, acc1 = 0.f, acc2 = 0.f;
    int cnt0 = 0, cnt1 = 0, cnt2 = 0;

    unsigned long long pos = lo;
    while (pos < hi) {
        if (pos < (unsigned long long)L0_F4) {
            const unsigned li = (unsigned)pos;
            const int b = (int)(li / (L0_F4 / NB));           // 409600 f4/batch
            const unsigned bend = (unsigned)(b + 1) * (L0_F4 / NB);
            const unsigned hcl = (hi < (unsigned long long)L0_F4) ? (unsigned)hi : L0_F4;
            const unsigned liend = bend < hcl ? bend : hcl;
            do_segment<80>(p0, t0, li, liend, b, bboxes, batch_idx, &sb, acc0, cnt0);
            pos = liend;
        } else if (pos < (unsigned long long)(L0_F4 + L1_F4)) {
            const unsigned li = (unsigned)(pos - L0_F4);
            const int b = (int)(li / (L1_F4 / NB));           // 102400 f4/batch
            const unsigned bend = (unsigned)(b + 1) * (L1_F4 / NB);
            const unsigned long long hrel = hi - L0_F4;
            const unsigned hcl = (hrel < (unsigned long long)L1_F4) ? (unsigned)hrel : L1_F4;
            const unsigned liend = bend < hcl ? bend : hcl;
            do_segment<40>(p1, t1, li, liend, b, bboxes, batch_idx, &sb, acc1, cnt1);
            pos = (unsigned long long)L0_F4 + liend;
        } else {
            const unsigned li = (unsigned)(pos - L0_F4 - L1_F4);
            const int b = (int)(li / (L2_F4 / NB));           // 25600 f4/batch
            const unsigned bend = (unsigned)(b + 1) * (L2_F4 / NB);
            const unsigned long long hrel = hi - L0_F4 - L1_F4;
            const unsigned hcl = (hrel < (unsigned long long)L2_F4) ? (unsigned)hrel : L2_F4;
            const unsigned liend = bend < hcl ? bend : hcl;
            do_segment<20>(p2, t2, li, liend, b, bboxes, batch_idx, &sb, acc2, cnt2);
            pos = (unsigned long long)(L0_F4 + L1_F4) + liend;
        }
    }

    __shared__ float smf[32];
    __shared__ int smi[32];
    __syncthreads();
    acc0 = block_sum_f(acc0, smf);
    acc1 = block_sum_f(acc1, smf);
    acc2 = block_sum_f(acc2, smf);
    cnt0 = block_sum_i(cnt0, smi);
    cnt1 = block_sum_i(cnt1, smi);
    cnt2 = block_sum_i(cnt2, smi);

    __shared__ bool s_last;
    if (threadIdx.x == 0) {
        g_pa[0][blockIdx.x] = acc0;
        g_pa[1][blockIdx.x] = acc1;
        g_pa[2][blockIdx.x] = acc2;
        g_pc[0][blockIdx.x] = cnt0;
        g_pc[1][blockIdx.x] = cnt1;
        g_pc[2][blockIdx.x] = cnt2;
        __threadfence();
        unsigned nfin = atomicAdd(&g_ticket, 1u);
        s_last = (nfin == GRID_BLOCKS - 1);
    }
    __syncthreads();
    if (!s_last) return;

    // ---- finalize (last block only) ----
    float fa0 = 0.f, fa1 = 0.f, fa2 = 0.f;
    int fc0 = 0, fc1 = 0, fc2 = 0;
    for (int i = threadIdx.x; i < GRID_BLOCKS; i += BLOCK_THREADS) {
        fa0 += g_pa[0][i]; fa1 += g_pa[1][i]; fa2 += g_pa[2][i];
        fc0 += g_pc[0][i]; fc1 += g_pc[1][i]; fc2 += g_pc[2][i];
    }
    fa0 = block_sum_f(fa0, smf);
    fa1 = block_sum_f(fa1, smf);
    fa2 = block_sum_f(fa2, smf);
    fc0 = block_sum_i(fc0, smi);
    fc1 = block_sum_i(fc1, smi);
    fc2 = block_sum_i(fc2, smi);

    if (threadIdx.x == 0) {
        double L = (double)fa0 / (double)fc0 +
                   (double)fa1 / (double)fc1 +
                   (double)fa2 / (double)fc2;
        out[0] = (float)(L / 3.0);
        __threadfence();
        g_ticket = 0;   // restore for next graph replay
    }
}

// ---------------------------------------------------------------------------
extern "C" void kernel_launch(void* const* d_in, const int* in_sizes, int n_in,
                              void* d_out, int out_size) {
    // input order: pred0, true0, pred1, true1, pred2, true2, bboxes, batch_idx, cls
    const float4* p0 = (const float4*)d_in[0];
    const float4* t0 = (const float4*)d_in[1];
    const float4* p1 = (const float4*)d_in[2];
    const float4* t1 = (const float4*)d_in[3];
    const float4* p2 = (const float4*)d_in[4];
    const float4* t2 = (const float4*)d_in[5];
    const float* bboxes = (const float*)d_in[6];
    const int* batch_idx = (const int*)d_in[7];

    fused_kernel<<<GRID_BLOCKS, BLOCK_THREADS>>>(p0, t0, p1, t1, p2, t2,
                                                 bboxes, batch_idx,
                                                 (float*)d_out);
}

// round 5
// speedup vs baseline: 1.3098x; 1.3098x over previous
#include <cuda_runtime.h>

// ---------------------------------------------------------------------------
// Masked multi-level MSE loss (B=16, C=256, T=128, S in {80,40,20}):
//   L = mean_l [ sum((M_l * (p_l - t_l))^2) / (C * sum(M_l)) ]
//
// kernel 1 (mask): per-(batch,level) box rasterization into uint8 masks +
//   per-block positive-cell counts (non-atomic partials).
// kernel 2 (reduce): channel-loop layout — each work unit = one spatial f4
//   position x CPU channels. Mask word loaded ONCE per unit, converted to 4
//   float multipliers in registers; inner loop is 2x LDG.128 + FP only.
//   Units per level are identical (409600) with CPU={16,4,1}.
//   Fully-masked-out units skip their data loads (saves ~10% DRAM).
//   Last block finalizes into d_out (self-resetting ticket).
// ---------------------------------------------------------------------------

#define NB 16
#define NT 128
#define NC 256
#define GRID_BLOCKS 1184                 // 148 SMs * 8
#define BLOCK_THREADS 256
#define THREADS_TOTAL (GRID_BLOCKS * BLOCK_THREADS)   // 303104

__device__ unsigned char g_mask0[NB * 80 * 80];
__device__ unsigned char g_mask1[NB * 40 * 40];
__device__ unsigned char g_mask2[NB * 20 * 20];

__device__ int   g_mcnt[3][NB][25];      // per-(lvl,batch,chunk) positive cells
__device__ float g_pa[3][GRID_BLOCKS];   // per-block sum-of-squares partials
__device__ unsigned g_ticket = 0;

// ---------------------------------------------------------------------------
// blockIdx = (cell_chunk, level, batch). Batch-filtered box compaction.
__global__ void mask_kernel(const float* __restrict__ bboxes,
                            const int* __restrict__ batch_idx) {
    const int lvl = blockIdx.y;
    const int b   = blockIdx.z;
    const int S = (lvl == 0) ? 80 : (lvl == 1) ? 40 : 20;
    const int cells = S * S;

    if ((int)(blockIdx.x * blockDim.x) >= cells) {
        if (threadIdx.x == 0) g_mcnt[lvl][b][blockIdx.x] = 0;
        return;
    }

    __shared__ int   nb;
    __shared__ short sxl[NT], sxr[NT], syt[NT], syd[NT];

    if (threadIdx.x == 0) nb = 0;
    __syncthreads();
    if (threadIdx.x < NT && batch_idx[threadIdx.x] == b) {
        const int t = threadIdx.x;
        const float fS = (float)S;
        int xc = (int)floorf(bboxes[t * 4 + 0] * fS);
        int yc = (int)floorf(bboxes[t * 4 + 1] * fS);
        int w  = (int)floorf(bboxes[t * 4 + 2] * fS);
        int h  = (int)floorf(bboxes[t * 4 + 3] * fS);
        int slot = atomicAdd(&nb, 1);
        sxl[slot] = (short)max(xc - w / 2, 0);
        syt[slot] = (short)max(yc - h / 2, 0);
        sxr[slot] = (short)min(xc + w / 2, S - 1);
        syd[slot] = (short)min(yc + h / 2, S - 1);
    }
    __syncthreads();

    const int idx = blockIdx.x * blockDim.x + threadIdx.x;
    int m = 0;
    if (idx < cells) {
        const int y = idx / S;
        const int x = idx % S;
        const int n = nb;
        for (int t = 0; t < n; t++) {
            m |= (x >= (int)sxl[t]) & (x <= (int)sxr[t]) &
                 (y >= (int)syt[t]) & (y <= (int)syd[t]);
        }
        unsigned char* mk = (lvl == 0) ? g_mask0 : (lvl == 1) ? g_mask1 : g_mask2;
        mk[b * cells + idx] = (unsigned char)m;
    }

    // per-block positive count (non-atomic partial)
    unsigned bal = __ballot_sync(0xffffffffu, m != 0);
    __shared__ int wsum[8];
    const int lane = threadIdx.x & 31, warp = threadIdx.x >> 5;
    if (lane == 0) wsum[warp] = __popc(bal);
    __syncthreads();
    if (threadIdx.x == 0) {
        int s = 0;
        for (int i = 0; i < 8; i++) s += wsum[i];
        g_mcnt[lvl][b][blockIdx.x] = s;
    }
}

// ---------------------------------------------------------------------------
__device__ __forceinline__ float block_sum_f(float v, float* sm) {
#pragma unroll
    for (int o = 16; o; o >>= 1) v += __shfl_down_sync(0xffffffffu, v, o);
    const int lane = threadIdx.x & 31, warp = threadIdx.x >> 5;
    if (lane == 0) sm[warp] = v;
    __syncthreads();
    v = (threadIdx.x < (BLOCK_THREADS / 32)) ? sm[threadIdx.x] : 0.f;
    if (warp == 0) {
#pragma unroll
        for (int o = 16; o; o >>= 1) v += __shfl_down_sync(0xffffffffu, v, o);
    }
    __syncthreads();
    return v;
}

__device__ __forceinline__ int block_sum_i(int v, int* sm) {
#pragma unroll
    for (int o = 16; o; o >>= 1) v += __shfl_down_sync(0xffffffffu, v, o);
    const int lane = threadIdx.x & 31, warp = threadIdx.x >> 5;
    if (lane == 0) sm[warp] = v;
    __syncthreads();
    v = (threadIdx.x < (BLOCK_THREADS / 32)) ? sm[threadIdx.x] : 0;
    if (warp == 0) {
#pragma unroll
        for (int o = 16; o; o >>= 1) v += __shfl_down_sync(0xffffffffu, v, o);
    }
    __syncthreads();
    return v;
}

// ---------------------------------------------------------------------------
// One unit = one spatial f4 position x CPU channels. U = 409600 per level.
template <int S, int CPU>
__device__ __forceinline__ float level_sumsq(const float4* __restrict__ p,
                                             const float4* __restrict__ q,
                                             const unsigned char* __restrict__ mask,
                                             unsigned gid) {
    constexpr unsigned CH4 = (unsigned)S * (S / 4);   // f4 per channel image
    constexpr unsigned POS = (unsigned)NB * CH4;      // spatial f4 positions
    constexpr unsigned U   = POS * ((unsigned)NC / (unsigned)CPU);

    float acc = 0.f;
#pragma unroll 1
    for (unsigned u = gid; u < U; u += (unsigned)THREADS_TOTAL) {
        const unsigned pos   = u % POS;
        const unsigned chunk = u / POS;
        const unsigned b     = pos / CH4;
        const unsigned posr  = pos - b * CH4;

        const unsigned mw = *(const unsigned*)(mask + b * (unsigned)(S * S) + 4u * posr);
        if (mw == 0) continue;   // whole f4 masked out: skip all CPU channel loads

        const float fm0 = __uint_as_float((mw & 1u)         * 0x3F800000u);
        const float fm1 = __uint_as_float(((mw >> 8) & 1u)  * 0x3F800000u);
        const float fm2 = __uint_as_float(((mw >> 16) & 1u) * 0x3F800000u);
        const float fm3 = __uint_as_float(((mw >> 24) & 1u) * 0x3F800000u);

        unsigned idx = b * ((unsigned)NC * CH4) + chunk * ((unsigned)CPU * CH4) + posr;

        if constexpr (CPU == 1) {
            const float4 a0 = __ldg(p + idx);
            const float4 c0 = __ldg(q + idx);
            float d, e;
            d = a0.x - c0.x; e = fm0 * d; acc = fmaf(e, d, acc);
            d = a0.y - c0.y; e = fm1 * d; acc = fmaf(e, d, acc);
            d = a0.z - c0.z; e = fm2 * d; acc = fmaf(e, d, acc);
            d = a0.w - c0.w; e = fm3 * d; acc = fmaf(e, d, acc);
        } else {
#pragma unroll 1
            for (int cc = 0; cc < CPU; cc += 2) {
                const float4 a0 = __ldg(p + idx);
                const float4 c0 = __ldg(q + idx);
                const float4 a1 = __ldg(p + idx + CH4);
                const float4 c1 = __ldg(q + idx + CH4);
                float d, e;
                d = a0.x - c0.x; e = fm0 * d; acc = fmaf(e, d, acc);
                d = a0.y - c0.y; e = fm1 * d; acc = fmaf(e, d, acc);
                d = a0.z - c0.z; e = fm2 * d; acc = fmaf(e, d, acc);
                d = a0.w - c0.w; e = fm3 * d; acc = fmaf(e, d, acc);
                d = a1.x - c1.x; e = fm0 * d; acc = fmaf(e, d, acc);
                d = a1.y - c1.y; e = fm1 * d; acc = fmaf(e, d, acc);
                d = a1.z - c1.z; e = fm2 * d; acc = fmaf(e, d, acc);
                d = a1.w - c1.w; e = fm3 * d; acc = fmaf(e, d, acc);
                idx += 2u * CH4;
            }
        }
    }
    return acc;
}

// ---------------------------------------------------------------------------
__global__ void __launch_bounds__(BLOCK_THREADS, 8)
reduce_kernel(const float4* __restrict__ p0, const float4* __restrict__ t0,
              const float4* __restrict__ p1, const float4* __restrict__ t1,
              const float4* __restrict__ p2, const float4* __restrict__ t2,
              float* __restrict__ out) {
    const unsigned gid = blockIdx.x * BLOCK_THREADS + threadIdx.x;

    float a0 = level_sumsq<80, 16>(p0, t0, g_mask0, gid);
    float a1 = level_sumsq<40, 4>(p1, t1, g_mask1, gid);
    float a2 = level_sumsq<20, 1>(p2, t2, g_mask2, gid);

    __shared__ float smf[32];
    __shared__ int smi[32];
    a0 = block_sum_f(a0, smf);
    a1 = block_sum_f(a1, smf);
    a2 = block_sum_f(a2, smf);

    __shared__ bool s_last;
    if (threadIdx.x == 0) {
        g_pa[0][blockIdx.x] = a0;
        g_pa[1][blockIdx.x] = a1;
        g_pa[2][blockIdx.x] = a2;
        __threadfence();
        unsigned n = atomicAdd(&g_ticket, 1u);
        s_last = (n == GRID_BLOCKS - 1);
    }
    __syncthreads();
    if (!s_last) return;

    // ---- finalize (last block only) ----
    float fa0 = 0.f, fa1 = 0.f, fa2 = 0.f;
    for (int i = threadIdx.x; i < GRID_BLOCKS; i += BLOCK_THREADS) {
        fa0 += g_pa[0][i]; fa1 += g_pa[1][i]; fa2 += g_pa[2][i];
    }
    int fc0 = 0, fc1 = 0, fc2 = 0;
    const int* mc = &g_mcnt[0][0][0];
    for (int i = threadIdx.x; i < NB * 25; i += BLOCK_THREADS) {
        fc0 += mc[i];
        fc1 += mc[NB * 25 + i];
        fc2 += mc[2 * NB * 25 + i];
    }
    fa0 = block_sum_f(fa0, smf);
    fa1 = block_sum_f(fa1, smf);
    fa2 = block_sum_f(fa2, smf);
    fc0 = block_sum_i(fc0, smi);
    fc1 = block_sum_i(fc1, smi);
    fc2 = block_sum_i(fc2, smi);

    if (threadIdx.x == 0) {
        double L = (double)fa0 / (256.0 * (double)fc0) +
                   (double)fa1 / (256.0 * (double)fc1) +
                   (double)fa2 / (256.0 * (double)fc2);
        out[0] = (float)(L / 3.0);
        __threadfence();
        g_ticket = 0;   // restore for next graph replay
    }
}

// ---------------------------------------------------------------------------
extern "C" void kernel_launch(void* const* d_in, const int* in_sizes, int n_in,
                              void* d_out, int out_size) {
    // input order: pred0, true0, pred1, true1, pred2, true2, bboxes, batch_idx, cls
    const float4* p0 = (const float4*)d_in[0];
    const float4* t0 = (const float4*)d_in[1];
    const float4* p1 = (const float4*)d_in[2];
    const float4* t1 = (const float4*)d_in[3];
    const float4* p2 = (const float4*)d_in[4];
    const float4* t2 = (const float4*)d_in[5];
    const float* bboxes = (const float*)d_in[6];
    const int* batch_idx = (const int*)d_in[7];

    mask_kernel<<<dim3(25, 3, 16), 256>>>(bboxes, batch_idx);
    reduce_kernel<<<GRID_BLOCKS, BLOCK_THREADS>>>(p0, t0, p1, t1, p2, t2,
                                                  (float*)d_out);
}

// round 6
// speedup vs baseline: 1.4154x; 1.0806x over previous
#include <cuda_runtime.h>

// ---------------------------------------------------------------------------
// Masked multi-level MSE loss (B=16, C=256, T=128, S in {80,40,20}):
//   L = mean_l [ sum((M_l * (p_l - t_l))^2) / (C * sum(M_l)) ]
//
// Single fused kernel, one wave of 592 blocks (148 SMs x 4, 64-reg budget).
// Each block: builds an SMEM box table (128 boxes counting-sorted by batch,
// per-level integer coords), then streams its balanced contiguous unit range
// per level. A unit = one spatial float4 position x CPU channels; its 4-cell
// mask is computed INLINE from the box table (no mask arrays, no mask loads).
// Inner loop: 8 independent LDG.128 per step. Positive-cell count taken on
// chunk==0 units (each position counted exactly once chip-wide).
// Last block finalizes into d_out (self-resetting ticket).
// ---------------------------------------------------------------------------

#define NB 16
#define NT 128
#define NC 256
#define GRID_BLOCKS 592
#define BT 256

__device__ float g_pa[3][GRID_BLOCKS];
__device__ int   g_pc[3][GRID_BLOCKS];
__device__ unsigned g_ticket = 0;

struct BoxTab {
    short4 box[3][NT];   // per level, sorted by batch: x=xl, y=xr, z=yt, w=yd
    int off[NB + 1];     // batch -> [off[b], off[b+1]) in box[]
    int cnt[NB];
};

// ---------------------------------------------------------------------------
__device__ __forceinline__ float block_sum_f(float v, float* sm) {
#pragma unroll
    for (int o = 16; o; o >>= 1) v += __shfl_down_sync(0xffffffffu, v, o);
    const int lane = threadIdx.x & 31, warp = threadIdx.x >> 5;
    if (lane == 0) sm[warp] = v;
    __syncthreads();
    v = (threadIdx.x < (BT / 32)) ? sm[threadIdx.x] : 0.f;
    if (warp == 0) {
#pragma unroll
        for (int o = 16; o; o >>= 1) v += __shfl_down_sync(0xffffffffu, v, o);
    }
    __syncthreads();
    return v;
}

__device__ __forceinline__ int block_sum_i(int v, int* sm) {
#pragma unroll
    for (int o = 16; o; o >>= 1) v += __shfl_down_sync(0xffffffffu, v, o);
    const int lane = threadIdx.x & 31, warp = threadIdx.x >> 5;
    if (lane == 0) sm[warp] = v;
    __syncthreads();
    v = (threadIdx.x < (BT / 32)) ? sm[threadIdx.x] : 0;
    if (warp == 0) {
#pragma unroll
        for (int o = 16; o; o >>= 1) v += __shfl_down_sync(0xffffffffu, v, o);
    }
    __syncthreads();
    return v;
}

// ---------------------------------------------------------------------------
// Stream one level. Unit = spatial f4 position x CPU channels (CPU % 4 == 0).
template <int S, int CPU>
__device__ __forceinline__ void level_sum(const float4* __restrict__ p,
                                          const float4* __restrict__ q,
                                          const BoxTab* tb, int lvl,
                                          float& acc_out, int& cnt_out) {
    constexpr unsigned S4   = (unsigned)S / 4;
    constexpr unsigned CH4  = (unsigned)S * S4;        // f4 per channel image
    constexpr unsigned POS  = (unsigned)NB * CH4;      // spatial f4 positions
    constexpr unsigned U    = POS * ((unsigned)NC / (unsigned)CPU);

    const unsigned lo = (unsigned)((unsigned long long)blockIdx.x * U / GRID_BLOCKS);
    const unsigned hi = (unsigned)((unsigned long long)(blockIdx.x + 1) * U / GRID_BLOCKS);

    const short4* __restrict__ boxes = tb->box[lvl];
    float acc0 = 0.f, acc1 = 0.f;
    int cnt = 0;

#pragma unroll 1
    for (unsigned u = lo + threadIdx.x; u < hi; u += BT) {
        const unsigned chunk = u / POS;
        const unsigned pos   = u - chunk * POS;
        const unsigned b     = pos / CH4;
        const unsigned posr  = pos - b * CH4;
        const int y  = (int)(posr / S4);
        const int x0 = 4 * (int)(posr - (unsigned)y * S4);

        // inline 4-cell mask from the box table
        int m = 0;
        const int j1 = tb->off[b + 1];
#pragma unroll 1
        for (int j = tb->off[b]; j < j1; j++) {
            const short4 bx = boxes[j];
            if (y >= (int)bx.z && y <= (int)bx.w) {
                int l = (int)bx.x - x0; l = l < 0 ? 0 : l;
                int r = (int)bx.y - x0; r = r > 3 ? 3 : r;
                if (l <= r) m |= (0xF << l) & (0xF >> (3 - r));
            }
        }
        if (chunk == 0) cnt += __popc(m);
        if (m == 0) continue;

        const float fm0 = __uint_as_float(( m       & 1) * 0x3F800000u);
        const float fm1 = __uint_as_float(((m >> 1) & 1) * 0x3F800000u);
        const float fm2 = __uint_as_float(((m >> 2) & 1) * 0x3F800000u);
        const float fm3 = __uint_as_float(((m >> 3) & 1) * 0x3F800000u);

        unsigned idx = b * ((unsigned)NC * CH4) + chunk * ((unsigned)CPU * CH4) + posr;
#pragma unroll 1
        for (int cc = 0; cc < CPU; cc += 4) {
            const float4 a0 = __ldg(p + idx);
            const float4 a1 = __ldg(p + idx + CH4);
            const float4 a2 = __ldg(p + idx + 2u * CH4);
            const float4 a3 = __ldg(p + idx + 3u * CH4);
            const float4 c0 = __ldg(q + idx);
            const float4 c1 = __ldg(q + idx + CH4);
            const float4 c2 = __ldg(q + idx + 2u * CH4);
            const float4 c3 = __ldg(q + idx + 3u * CH4);
            float d, e;
            d = a0.x - c0.x; e = fm0 * d; acc0 = fmaf(e, d, acc0);
            d = a0.y - c0.y; e = fm1 * d; acc1 = fmaf(e, d, acc1);
            d = a0.z - c0.z; e = fm2 * d; acc0 = fmaf(e, d, acc0);
            d = a0.w - c0.w; e = fm3 * d; acc1 = fmaf(e, d, acc1);
            d = a1.x - c1.x; e = fm0 * d; acc0 = fmaf(e, d, acc0);
            d = a1.y - c1.y; e = fm1 * d; acc1 = fmaf(e, d, acc1);
            d = a1.z - c1.z; e = fm2 * d; acc0 = fmaf(e, d, acc0);
            d = a1.w - c1.w; e = fm3 * d; acc1 = fmaf(e, d, acc1);
            d = a2.x - c2.x; e = fm0 * d; acc0 = fmaf(e, d, acc0);
            d = a2.y - c2.y; e = fm1 * d; acc1 = fmaf(e, d, acc1);
            d = a2.z - c2.z; e = fm2 * d; acc0 = fmaf(e, d, acc0);
            d = a2.w - c2.w; e = fm3 * d; acc1 = fmaf(e, d, acc1);
            d = a3.x - c3.x; e = fm0 * d; acc0 = fmaf(e, d, acc0);
            d = a3.y - c3.y; e = fm1 * d; acc1 = fmaf(e, d, acc1);
            d = a3.z - c3.z; e = fm2 * d; acc0 = fmaf(e, d, acc0);
            d = a3.w - c3.w; e = fm3 * d; acc1 = fmaf(e, d, acc1);
            idx += 4u * CH4;
        }
    }
    acc_out = acc0 + acc1;
    cnt_out = cnt;
}

// ---------------------------------------------------------------------------
__global__ void __launch_bounds__(BT, 4)
fused_kernel(const float4* __restrict__ p0, const float4* __restrict__ t0,
             const float4* __restrict__ p1, const float4* __restrict__ t1,
             const float4* __restrict__ p2, const float4* __restrict__ t2,
             const float* __restrict__ bboxes,
             const int* __restrict__ batch_idx,
             float* __restrict__ out) {
    __shared__ BoxTab tb;
    __shared__ float smf[32];
    __shared__ int smi[32];

    // ---- build box table (counting sort by batch; order within batch free) --
    if (threadIdx.x < NB) tb.cnt[threadIdx.x] = 0;
    __syncthreads();
    int myb = 0, myrank = 0;
    float4 bb;
    if (threadIdx.x < NT) {
        myb = batch_idx[threadIdx.x];
        bb = ((const float4*)bboxes)[threadIdx.x];
        myrank = atomicAdd(&tb.cnt[myb], 1);
    }
    __syncthreads();
    if (threadIdx.x == 0) {
        int s = 0;
        tb.off[0] = 0;
#pragma unroll
        for (int i = 0; i < NB; i++) { s += tb.cnt[i]; tb.off[i + 1] = s; }
    }
    __syncthreads();
    if (threadIdx.x < NT) {
        const int g = tb.off[myb] + myrank;
#pragma unroll
        for (int lvl = 0; lvl < 3; lvl++) {
            const int S = (lvl == 0) ? 80 : (lvl == 1) ? 40 : 20;
            const float fS = (float)S;
            int xc = (int)floorf(bb.x * fS);
            int yc = (int)floorf(bb.y * fS);
            int w  = (int)floorf(bb.z * fS);
            int h  = (int)floorf(bb.w * fS);
            short xl = (short)max(xc - w / 2, 0);
            short yt = (short)max(yc - h / 2, 0);
            short xr = (short)min(xc + w / 2, S - 1);
            short yd = (short)min(yc + h / 2, S - 1);
            tb.box[lvl][g] = make_short4(xl, xr, yt, yd);
        }
    }
    __syncthreads();

    // ---- stream all three levels ----
    float a0, a1, a2;
    int c0, c1, c2;
    level_sum<80, 16>(p0, t0, &tb, 0, a0, c0);
    level_sum<40, 4>(p1, t1, &tb, 1, a1, c1);
    level_sum<20, 4>(p2, t2, &tb, 2, a2, c2);

    a0 = block_sum_f(a0, smf);
    a1 = block_sum_f(a1, smf);
    a2 = block_sum_f(a2, smf);
    c0 = block_sum_i(c0, smi);
    c1 = block_sum_i(c1, smi);
    c2 = block_sum_i(c2, smi);

    __shared__ bool s_last;
    if (threadIdx.x == 0) {
        g_pa[0][blockIdx.x] = a0;
        g_pa[1][blockIdx.x] = a1;
        g_pa[2][blockIdx.x] = a2;
        g_pc[0][blockIdx.x] = c0;
        g_pc[1][blockIdx.x] = c1;
        g_pc[2][blockIdx.x] = c2;
        __threadfence();
        unsigned n = atomicAdd(&g_ticket, 1u);
        s_last = (n == GRID_BLOCKS - 1);
    }
    __syncthreads();
    if (!s_last) return;

    // ---- finalize (last block only) ----
    float fa0 = 0.f, fa1 = 0.f, fa2 = 0.f;
    int fc0 = 0, fc1 = 0, fc2 = 0;
    for (int i = threadIdx.x; i < GRID_BLOCKS; i += BT) {
        fa0 += g_pa[0][i]; fa1 += g_pa[1][i]; fa2 += g_pa[2][i];
        fc0 += g_pc[0][i]; fc1 += g_pc[1][i]; fc2 += g_pc[2][i];
    }
    fa0 = block_sum_f(fa0, smf);
    fa1 = block_sum_f(fa1, smf);
    fa2 = block_sum_f(fa2, smf);
    fc0 = block_sum_i(fc0, smi);
    fc1 = block_sum_i(fc1, smi);
    fc2 = block_sum_i(fc2, smi);

    if (threadIdx.x == 0) {
        double L = (double)fa0 / (256.0 * (double)fc0) +
                   (double)fa1 / (256.0 * (double)fc1) +
                   (double)fa2 / (256.0 * (double)fc2);
        out[0] = (float)(L / 3.0);
        __threadfence();
        g_ticket = 0;   // restore for next graph replay
    }
}

// ---------------------------------------------------------------------------
extern "C" void kernel_launch(void* const* d_in, const int* in_sizes, int n_in,
                              void* d_out, int out_size) {
    // input order: pred0, true0, pred1, true1, pred2, true2, bboxes, batch_idx, cls
    const float4* p0 = (const float4*)d_in[0];
    const float4* t0 = (const float4*)d_in[1];
    const float4* p1 = (const float4*)d_in[2];
    const float4* t1 = (const float4*)d_in[3];
    const float4* p2 = (const float4*)d_in[4];
    const float4* t2 = (const float4*)d_in[5];
    const float* bboxes = (const float*)d_in[6];
    const int* batch_idx = (const int*)d_in[7];

    fused_kernel<<<GRID_BLOCKS, BT>>>(p0, t0, p1, t1, p2, t2,
                                      bboxes, batch_idx, (float*)d_out);
}